// round 3
// baseline (speedup 1.0000x reference)
#include <cuda_runtime.h>
#include <math.h>

#define NROWS 65536      // 32*32*64
#define DIM   64
#define NE    1024
#define MT    128        // rows per CTA
#define NT    128        // codes per chunk
#define LDZ   65
#define LDE   65

// Output layout (float32, return-order flatten):
// [0]            loss
// [1 .. 4194304] z_q_st (== z_q)
// [4194305]      perplexity
// [4194306 .. ]  min_encoding_indices (as float)
#define ZQ_OFF   1
#define PERP_OFF (1 + NROWS*DIM)
#define IDX_OFF  (2 + NROWS*DIM)

// ---- scratch (no allocations allowed) ----
__device__ float  g_counts[NE];
__device__ float  g_en[NE];
__device__ double g_mse;
__device__ double g_edist;

// ============================================================
// init: zero accumulators, compute ||e||^2.
// MUST match jnp.sum(emb**2, axis=1): sequential k, UNFUSED
// (square rounded, then added) — no FMA contraction.
// ============================================================
__global__ void vq_init(const float* __restrict__ emb) {
    int t = threadIdx.x;           // 1024 threads
    if (t == 0) { g_mse = 0.0; g_edist = 0.0; }
    g_counts[t] = 0.0f;
    float s = 0.0f;
    const float* e = emb + t * DIM;
#pragma unroll
    for (int k = 0; k < DIM; k++) {
        float sq = __fmul_rn(e[k], e[k]);
        s = __fadd_rn(s, sq);
    }
    g_en[t] = s;
}

// ============================================================
// codebook pairwise distances: sum over ALL ordered (i,j) of
// sqrt(max(en_i + en_j - 2 e_i.e_j, 0)).  tril-mean = sum/2/n^2.
// (e_loss is a mean over 1M values -> reorder noise washes out
// below fp32 ulp; exactness not needed here.)
// ============================================================
__global__ __launch_bounds__(256) void vq_pairs(const float* __restrict__ emb) {
    __shared__ float ei[8][DIM];
    __shared__ float ej[128][LDE];
    __shared__ float eni_s[8];
    __shared__ float red[8];
    int tid = threadIdx.x;
    int i0  = blockIdx.x * 8;

    for (int v = tid; v < 8 * DIM; v += 256)
        ei[v >> 6][v & 63] = emb[i0 * DIM + v];
    if (tid < 8) eni_s[tid] = g_en[i0 + tid];

    float sum = 0.0f;
    for (int jc = 0; jc < NE; jc += 128) {
        __syncthreads();
#pragma unroll
        for (int t = 0; t < 8; t++) {
            int v  = tid + t * 256;
            int jl = v >> 4, c4 = (v & 15) << 2;
            float4 f = *reinterpret_cast<const float4*>(emb + (jc + jl) * DIM + c4);
            ej[jl][c4 + 0] = f.x; ej[jl][c4 + 1] = f.y;
            ej[jl][c4 + 2] = f.z; ej[jl][c4 + 3] = f.w;
        }
        __syncthreads();
        int il = tid >> 5, lane = tid & 31;
#pragma unroll
        for (int jj = 0; jj < 4; jj++) {
            int jl = lane + 32 * jj;
            float dot = 0.0f;
#pragma unroll 16
            for (int k = 0; k < DIM; k++)
                dot = fmaf(ei[il][k], ej[jl][k], dot);
            float d2 = eni_s[il] + g_en[jc + jl] - 2.0f * dot;
            sum += sqrtf(fmaxf(d2, 0.0f));
        }
    }
#pragma unroll
    for (int off = 16; off > 0; off >>= 1)
        sum += __shfl_down_sync(0xffffffffu, sum, off);
    if ((tid & 31) == 0) red[tid >> 5] = sum;
    __syncthreads();
    if (tid == 0) {
        float s = 0.0f;
#pragma unroll
        for (int w = 0; w < 8; w++) s += red[w];
        atomicAdd(&g_edist, (double)s);
    }
}

// ============================================================
// main: per-row argmin over 1024 codes, replicating the
// reference's EXACT fp32 rounding chain:
//   d = fl( fl(zsq_i + en_j) - fl(2*dot_ij) )
// dot: sequential ascending-k FMA (matches fp32 GEMM k-order).
// zsq: sequential UNFUSED sum of squares (matches XLA reduce).
// Then gather z_q, write indices, histogram, mse accumulation.
// ============================================================
__global__ __launch_bounds__(256) void vq_main(const float* __restrict__ z,
                                               const float* __restrict__ emb,
                                               float* __restrict__ out) {
    extern __shared__ float smem[];
    float (*zs)[LDZ] = (float(*)[LDZ])smem;
    float (*es)[LDE] = (float(*)[LDE])(smem + MT * LDZ);
    float* szs       = smem + MT * LDZ + NT * LDE;          // [MT] row ||z||^2
    int*   ridx      = (int*)(szs + MT);
    float* red       = (float*)(ridx + MT);

    const int tid = threadIdx.x;
    const int tx  = tid & 15, ty = tid >> 4;
    const int m0  = blockIdx.x * MT;

    // load z tile [128][64] (row-major, LD=65)
#pragma unroll
    for (int t = 0; t < 8; t++) {
        int v = tid + t * 256;
        int row = v >> 4, c4 = (v & 15) << 2;
        float4 f = *reinterpret_cast<const float4*>(z + (m0 + row) * DIM + c4);
        zs[row][c4 + 0] = f.x; zs[row][c4 + 1] = f.y;
        zs[row][c4 + 2] = f.z; zs[row][c4 + 3] = f.w;
    }
    __syncthreads();

    // zsq per row: sequential, UNFUSED (square rounded, then added),
    // exactly jnp.sum(zf**2, axis=1).
    if (tid < MT) {
        float s = 0.0f;
#pragma unroll
        for (int k = 0; k < DIM; k++) {
            float sq = __fmul_rn(zs[tid][k], zs[tid][k]);
            s = __fadd_rn(s, sq);
        }
        szs[tid] = s;
    }

    float minv[8];
    int   mini[8];
#pragma unroll
    for (int i = 0; i < 8; i++) { minv[i] = 3.4e38f; mini[i] = 0; }

    float Srow[8];
    bool have_S = false;

    for (int n0 = 0; n0 < NE; n0 += NT) {
        __syncthreads();
        if (!have_S) {
            // szs written before this barrier -> safe to read after it
#pragma unroll
            for (int i = 0; i < 8; i++) Srow[i] = szs[ty + 16 * i];
            have_S = true;
        }
#pragma unroll
        for (int t = 0; t < 8; t++) {
            int v = tid + t * 256;
            int cl = v >> 4, c4 = (v & 15) << 2;
            float4 f = *reinterpret_cast<const float4*>(emb + (n0 + cl) * DIM + c4);
            es[cl][c4 + 0] = f.x; es[cl][c4 + 1] = f.y;
            es[cl][c4 + 2] = f.z; es[cl][c4 + 3] = f.w;
        }
        __syncthreads();

        float dot[8][8];
#pragma unroll
        for (int i = 0; i < 8; i++)
#pragma unroll
            for (int j = 0; j < 8; j++) dot[i][j] = 0.0f;

#pragma unroll 8
        for (int k = 0; k < DIM; k++) {
            float a[8], b[8];
#pragma unroll
            for (int i = 0; i < 8; i++) a[i] = zs[ty + 16 * i][k];  // broadcast
#pragma unroll
            for (int j = 0; j < 8; j++) b[j] = es[tx + 16 * j][k];  // stride 65 -> conflict-free
#pragma unroll
            for (int i = 0; i < 8; i++)
#pragma unroll
                for (int j = 0; j < 8; j++)
                    dot[i][j] = fmaf(a[i], b[j], dot[i][j]);   // sequential ascending k
        }

#pragma unroll
        for (int j = 0; j < 8; j++) {
            int code = n0 + tx + 16 * j;      // increasing in (n0, j) per thread
            float en = __ldg(&g_en[code]);
#pragma unroll
            for (int i = 0; i < 8; i++) {
                // d = fl( fl(S + en) - 2*dot ), 2*dot exact
                float t = __fadd_rn(Srow[i], en);
                float s = __fadd_rn(t, -2.0f * dot[i][j]);
                if (s < minv[i]) { minv[i] = s; mini[i] = code; }  // strict < keeps lowest code
            }
        }
    }

    // reduce across the 16 tx-lanes of each ty group (lowest-index tie-break)
#pragma unroll
    for (int off = 8; off > 0; off >>= 1) {
#pragma unroll
        for (int i = 0; i < 8; i++) {
            float ov = __shfl_down_sync(0xffffffffu, minv[i], off, 16);
            int   oi = __shfl_down_sync(0xffffffffu, mini[i], off, 16);
            if (ov < minv[i] || (ov == minv[i] && oi < mini[i])) {
                minv[i] = ov; mini[i] = oi;
            }
        }
    }
    if (tx == 0) {
#pragma unroll
        for (int i = 0; i < 8; i++) ridx[ty + 16 * i] = mini[i];
    }
    __syncthreads();

    if (tid < MT) atomicAdd(&g_counts[ridx[tid]], 1.0f);

    // gather z_q, write outputs, accumulate mse (all coalesced)
    float* zq   = out + ZQ_OFF;
    float* oidx = out + IDX_OFF;
    int col = tid & 63, r0 = tid >> 6;
    float lsum = 0.0f;
#pragma unroll 4
    for (int it = 0; it < 32; ++it) {
        int r   = r0 + 4 * it;
        int gi  = (m0 + r) * DIM + col;
        int idx = ridx[r];
        float q  = emb[idx * DIM + col];
        float zv = z[gi];
        zq[gi] = q;
        float d = q - zv;
        lsum = fmaf(d, d, lsum);
        if (col == 0) oidx[m0 + r] = (float)idx;
    }
#pragma unroll
    for (int off = 16; off > 0; off >>= 1)
        lsum += __shfl_down_sync(0xffffffffu, lsum, off);
    if ((tid & 31) == 0) red[tid >> 5] = lsum;
    __syncthreads();
    if (tid == 0) {
        float s = 0.0f;
#pragma unroll
        for (int w = 0; w < 8; w++) s += red[w];
        atomicAdd(&g_mse, (double)s);
    }
}

// ============================================================
// finalize: perplexity + loss scalars
// ============================================================
__global__ void vq_finalize(float* __restrict__ out) {
    __shared__ float red[32];
    int tid = threadIdx.x;   // 1024 threads
    float p = g_counts[tid] * (1.0f / (float)NROWS);
    float h = -p * logf(p + 1e-10f);
#pragma unroll
    for (int off = 16; off > 0; off >>= 1)
        h += __shfl_down_sync(0xffffffffu, h, off);
    if ((tid & 31) == 0) red[tid >> 5] = h;
    __syncthreads();
    if (tid == 0) {
        float H = 0.0f;
#pragma unroll
        for (int w = 0; w < 32; w++) H += red[w];
        float perp = expf(H);
        double mse = g_mse / (double)(NROWS * DIM);
        // mean(tril(e_d)) over n^2 entries; tril sum = full sum / 2 (symmetric, zero diag)
        double mean_tril = (g_edist * 0.5) / ((double)NE * (double)NE);
        double e_loss = exp(-mean_tril / 0.1);
        out[0]        = (float)(1.25 * mse + e_loss);
        out[PERP_OFF] = perp;
    }
}

// ============================================================
extern "C" void kernel_launch(void* const* d_in, const int* in_sizes, int n_in,
                              void* d_out, int out_size) {
    const float* z   = (const float*)d_in[0];
    const float* emb = (const float*)d_in[1];
    float* out = (float*)d_out;

    const int smem_bytes = (MT * LDZ + NT * LDE + MT + MT + 8) * (int)sizeof(float);
    cudaFuncSetAttribute(vq_main, cudaFuncAttributeMaxDynamicSharedMemorySize, smem_bytes);

    vq_init<<<1, 1024>>>(emb);
    vq_pairs<<<NE / 8, 256>>>(emb);
    vq_main<<<NROWS / MT, 256, smem_bytes>>>(z, emb, out);
    vq_finalize<<<1, 1024>>>(out);
}

// round 4
// speedup vs baseline: 1.0840x; 1.0840x over previous
#include <cuda_runtime.h>
#include <math.h>

#define NROWS 65536      // 32*32*64
#define DIM   64
#define NE    1024
#define MT    128        // rows per CTA
#define NT    128        // codes per chunk
#define LDT   130        // k-major leading dim (even -> 8B-aligned pairs)
#define LDE   65         // for vq_pairs only

// Output layout (float32, return-order flatten):
// [0]            loss
// [1 .. 4194304] z_q_st (== z_q)
// [4194305]      perplexity
// [4194306 .. ]  min_encoding_indices (as float)
#define ZQ_OFF   1
#define PERP_OFF (1 + NROWS*DIM)
#define IDX_OFF  (2 + NROWS*DIM)

// ---- scratch (no allocations allowed) ----
__device__ float  g_counts[NE];
__device__ float  g_en[NE];
__device__ double g_mse;
__device__ double g_edist;

// ============================================================
// init: zero accumulators, compute ||e||^2.
// MUST match jnp.sum(emb**2, axis=1): sequential k, UNFUSED.
// ============================================================
__global__ void vq_init(const float* __restrict__ emb) {
    int t = threadIdx.x;           // 1024 threads
    if (t == 0) { g_mse = 0.0; g_edist = 0.0; }
    g_counts[t] = 0.0f;
    float s = 0.0f;
    const float* e = emb + t * DIM;
#pragma unroll
    for (int k = 0; k < DIM; k++) {
        float sq = __fmul_rn(e[k], e[k]);
        s = __fadd_rn(s, sq);
    }
    g_en[t] = s;
}

// ============================================================
// codebook pairwise distances (e_loss): mean over 1M values,
// reorder noise below fp32 ulp -> no exactness needed.
// ============================================================
__global__ __launch_bounds__(256) void vq_pairs(const float* __restrict__ emb) {
    __shared__ float ei[8][DIM];
    __shared__ float ej[128][LDE];
    __shared__ float eni_s[8];
    __shared__ float red[8];
    int tid = threadIdx.x;
    int i0  = blockIdx.x * 8;

    for (int v = tid; v < 8 * DIM; v += 256)
        ei[v >> 6][v & 63] = emb[i0 * DIM + v];
    if (tid < 8) eni_s[tid] = g_en[i0 + tid];

    float sum = 0.0f;
    for (int jc = 0; jc < NE; jc += 128) {
        __syncthreads();
#pragma unroll
        for (int t = 0; t < 8; t++) {
            int v  = tid + t * 256;
            int jl = v >> 4, c4 = (v & 15) << 2;
            float4 f = *reinterpret_cast<const float4*>(emb + (jc + jl) * DIM + c4);
            ej[jl][c4 + 0] = f.x; ej[jl][c4 + 1] = f.y;
            ej[jl][c4 + 2] = f.z; ej[jl][c4 + 3] = f.w;
        }
        __syncthreads();
        int il = tid >> 5, lane = tid & 31;
#pragma unroll
        for (int jj = 0; jj < 4; jj++) {
            int jl = lane + 32 * jj;
            float dot = 0.0f;
#pragma unroll 16
            for (int k = 0; k < DIM; k++)
                dot = fmaf(ei[il][k], ej[jl][k], dot);
            float d2 = eni_s[il] + g_en[jc + jl] - 2.0f * dot;
            sum += sqrtf(fmaxf(d2, 0.0f));
        }
    }
#pragma unroll
    for (int off = 16; off > 0; off >>= 1)
        sum += __shfl_down_sync(0xffffffffu, sum, off);
    if ((tid & 31) == 0) red[tid >> 5] = sum;
    __syncthreads();
    if (tid == 0) {
        float s = 0.0f;
#pragma unroll
        for (int w = 0; w < 8; w++) s += red[w];
        atomicAdd(&g_edist, (double)s);
    }
}

// ============================================================
// main: per-row argmin over 1024 codes with EXACT fp32 chain
//   d = fl( fl(zsq_i + en_j) - fl(2*dot_ij) )
// dot: sequential ascending-k FMA, now via PACKED fma.rn.f32x2
// (two independent IEEE-rn FMAs -> bitwise identical per chain).
// k-major smem tiles; code-pairs packed free via LDS.64.
// Thread (tx,ty): rows 2ty+32*i2+{0,1}, codes 2tx+32*j2+{0,1}.
// ============================================================
__global__ __launch_bounds__(256) void vq_main(const float* __restrict__ z,
                                               const float* __restrict__ emb,
                                               float* __restrict__ out) {
    extern __shared__ float smem[];
    float (*zs_t)[LDT] = (float(*)[LDT])smem;                 // [64][130] k-major z tile
    float (*es_t)[LDT] = (float(*)[LDT])(smem + DIM * LDT);   // [64][130] k-major emb tile
    float* szs         = smem + 2 * DIM * LDT;                // [MT] row ||z||^2
    int*   ridx        = (int*)(szs + MT);
    float* red         = (float*)(ridx + MT);

    const int tid = threadIdx.x;
    const int tx  = tid & 15, ty = tid >> 4;
    const int m0  = blockIdx.x * MT;

    // transpose-load z tile: global [row][k] -> zs_t[k][row]
#pragma unroll
    for (int t = 0; t < 8; t++) {
        int v = tid + t * 256;
        int row = v >> 4, c4 = (v & 15) << 2;
        float4 f = *reinterpret_cast<const float4*>(z + (m0 + row) * DIM + c4);
        zs_t[c4 + 0][row] = f.x; zs_t[c4 + 1][row] = f.y;
        zs_t[c4 + 2][row] = f.z; zs_t[c4 + 3][row] = f.w;
    }
    __syncthreads();

    // zsq per row: sequential UNFUSED sum of squares (jnp.sum(zf**2)).
    if (tid < MT) {
        float s = 0.0f;
#pragma unroll
        for (int k = 0; k < DIM; k++) {
            float sq = __fmul_rn(zs_t[k][tid], zs_t[k][tid]);
            s = __fadd_rn(s, sq);
        }
        szs[tid] = s;
    }

    float minv[8];
    int   mini[8];
#pragma unroll
    for (int i = 0; i < 8; i++) { minv[i] = 3.4e38f; mini[i] = 0; }

    float Srow[8];
    bool have_S = false;

    for (int n0 = 0; n0 < NE; n0 += NT) {
        __syncthreads();
        if (!have_S) {
#pragma unroll
            for (int i = 0; i < 8; i++)
                Srow[i] = szs[2 * ty + 32 * (i >> 1) + (i & 1)];
            have_S = true;
        }
        // transpose-load emb tile: global [code][k] -> es_t[k][code_local]
#pragma unroll
        for (int t = 0; t < 8; t++) {
            int v = tid + t * 256;
            int cl = v >> 4, c4 = (v & 15) << 2;
            float4 f = *reinterpret_cast<const float4*>(emb + (n0 + cl) * DIM + c4);
            es_t[c4 + 0][cl] = f.x; es_t[c4 + 1][cl] = f.y;
            es_t[c4 + 2][cl] = f.z; es_t[c4 + 3][cl] = f.w;
        }
        __syncthreads();

        // 32 packed accumulators: dot2[i][j2] = (dot[i][2j2], dot[i][2j2+1])
        unsigned long long dot2[8][4];
#pragma unroll
        for (int i = 0; i < 8; i++)
#pragma unroll
            for (int j2 = 0; j2 < 4; j2++) dot2[i][j2] = 0ull;

#pragma unroll 4
        for (int k = 0; k < DIM; k++) {
            const float* zrow = &zs_t[k][2 * ty];
            const float* erow = &es_t[k][2 * tx];
            unsigned long long aa[8], b2[4];
#pragma unroll
            for (int i2 = 0; i2 < 4; i2++) {
                float2 av = *reinterpret_cast<const float2*>(zrow + 32 * i2);
                asm("mov.b64 %0, {%1, %1};" : "=l"(aa[2 * i2    ]) : "f"(av.x));
                asm("mov.b64 %0, {%1, %1};" : "=l"(aa[2 * i2 + 1]) : "f"(av.y));
                float2 bv = *reinterpret_cast<const float2*>(erow + 32 * i2);
                asm("mov.b64 %0, {%1, %2};" : "=l"(b2[i2]) : "f"(bv.x), "f"(bv.y));
            }
#pragma unroll
            for (int i = 0; i < 8; i++)
#pragma unroll
                for (int j2 = 0; j2 < 4; j2++)
                    asm("fma.rn.f32x2 %0, %1, %2, %0;"
                        : "+l"(dot2[i][j2]) : "l"(aa[i]), "l"(b2[j2]));
        }

        // score + argmin; codes visited in strictly ascending order per thread
#pragma unroll
        for (int j2 = 0; j2 < 4; j2++) {
            int code0 = n0 + 2 * tx + 32 * j2;
            float en0 = __ldg(&g_en[code0]);
            float en1 = __ldg(&g_en[code0 + 1]);
#pragma unroll
            for (int i = 0; i < 8; i++) {
                float dlo, dhi;
                asm("mov.b64 {%0, %1}, %2;" : "=f"(dlo), "=f"(dhi) : "l"(dot2[i][j2]));
                float s0 = __fadd_rn(__fadd_rn(Srow[i], en0), -2.0f * dlo);
                if (s0 < minv[i]) { minv[i] = s0; mini[i] = code0; }
                float s1 = __fadd_rn(__fadd_rn(Srow[i], en1), -2.0f * dhi);
                if (s1 < minv[i]) { minv[i] = s1; mini[i] = code0 + 1; }
            }
        }
    }

    // reduce across the 16 tx-lanes of each ty group (lowest-index tie-break)
#pragma unroll
    for (int off = 8; off > 0; off >>= 1) {
#pragma unroll
        for (int i = 0; i < 8; i++) {
            float ov = __shfl_down_sync(0xffffffffu, minv[i], off, 16);
            int   oi = __shfl_down_sync(0xffffffffu, mini[i], off, 16);
            if (ov < minv[i] || (ov == minv[i] && oi < mini[i])) {
                minv[i] = ov; mini[i] = oi;
            }
        }
    }
    if (tx == 0) {
#pragma unroll
        for (int i = 0; i < 8; i++)
            ridx[2 * ty + 32 * (i >> 1) + (i & 1)] = mini[i];
    }
    __syncthreads();

    if (tid < MT) atomicAdd(&g_counts[ridx[tid]], 1.0f);

    // gather z_q, write outputs, accumulate mse (all coalesced)
    float* zq   = out + ZQ_OFF;
    float* oidx = out + IDX_OFF;
    int col = tid & 63, r0 = tid >> 6;
    float lsum = 0.0f;
#pragma unroll 4
    for (int it = 0; it < 32; ++it) {
        int r   = r0 + 4 * it;
        int gi  = (m0 + r) * DIM + col;
        int idx = ridx[r];
        float q  = emb[idx * DIM + col];
        float zv = z[gi];
        zq[gi] = q;
        float d = q - zv;
        lsum = fmaf(d, d, lsum);
        if (col == 0) oidx[m0 + r] = (float)idx;
    }
#pragma unroll
    for (int off = 16; off > 0; off >>= 1)
        lsum += __shfl_down_sync(0xffffffffu, lsum, off);
    if ((tid & 31) == 0) red[tid >> 5] = lsum;
    __syncthreads();
    if (tid == 0) {
        float s = 0.0f;
#pragma unroll
        for (int w = 0; w < 8; w++) s += red[w];
        atomicAdd(&g_mse, (double)s);
    }
}

// ============================================================
// finalize: perplexity + loss scalars
// ============================================================
__global__ void vq_finalize(float* __restrict__ out) {
    __shared__ float red[32];
    int tid = threadIdx.x;   // 1024 threads
    float p = g_counts[tid] * (1.0f / (float)NROWS);
    float h = -p * logf(p + 1e-10f);
#pragma unroll
    for (int off = 16; off > 0; off >>= 1)
        h += __shfl_down_sync(0xffffffffu, h, off);
    if ((tid & 31) == 0) red[tid >> 5] = h;
    __syncthreads();
    if (tid == 0) {
        float H = 0.0f;
#pragma unroll
        for (int w = 0; w < 32; w++) H += red[w];
        float perp = expf(H);
        double mse = g_mse / (double)(NROWS * DIM);
        double mean_tril = (g_edist * 0.5) / ((double)NE * (double)NE);
        double e_loss = exp(-mean_tril / 0.1);
        out[0]        = (float)(1.25 * mse + e_loss);
        out[PERP_OFF] = perp;
    }
}

// ============================================================
extern "C" void kernel_launch(void* const* d_in, const int* in_sizes, int n_in,
                              void* d_out, int out_size) {
    const float* z   = (const float*)d_in[0];
    const float* emb = (const float*)d_in[1];
    float* out = (float*)d_out;

    const int smem_bytes = (2 * DIM * LDT + MT + MT + 8) * (int)sizeof(float);
    cudaFuncSetAttribute(vq_main, cudaFuncAttributeMaxDynamicSharedMemorySize, smem_bytes);

    vq_init<<<1, 1024>>>(emb);
    vq_pairs<<<NE / 8, 256>>>(emb);
    vq_main<<<NROWS / MT, 256, smem_bytes>>>(z, emb, out);
    vq_finalize<<<1, 1024>>>(out);
}